// round 16
// baseline (speedup 1.0000x reference)
#include <cuda_runtime.h>
#include <cuda_bf16.h>
#include <math.h>
#include <stdint.h>

#define BB 2
#define NN 2048
#define MM 2048
#define CC 512
#define KC 16        // K
#define KK1 8        // K1
#define KEY 1024
#define H1D 64
#define H2D 128

// ---------------- device scratch (no allocs allowed) ----------------
__device__ float g_scores[BB * NN * MM];   // 33.5 MB (unnormalized e = exp(-dist))
__device__ float g_xx[BB * NN];
__device__ float g_yy[BB * MM];
__device__ float g_rowpart[BB * NN * 64];  // per (row, m-block*2 + warp_n) partial sums of e
__device__ float g_rowinv[BB * NN];        // 1 / row sum of e
__device__ float g_corr[BB * 3 * NN];      // src_corr (B,3,N)
__device__ float g_rowmax[BB * NN];        // max of rmm row
__device__ float g_slogit[BB * NN];
__device__ float g_weight[BB * NN];
__device__ int   g_topi[BB * KEY];
__device__ float g_R[BB * 9];
__device__ float g_t[BB * 3];
// bf16 3-way split operands, K-major [b][n][c]
__device__ __nv_bfloat16 g_A1[BB * NN * CC];
__device__ __nv_bfloat16 g_A2[BB * NN * CC];
__device__ __nv_bfloat16 g_A3[BB * NN * CC];
__device__ __nv_bfloat16 g_B1[BB * MM * CC];
__device__ __nv_bfloat16 g_B2[BB * MM * CC];
__device__ __nv_bfloat16 g_B3[BB * MM * CC];

// ---------------- output layout offsets (fp32, tuple order) ----------------
#define OFF_R     0
#define OFF_T     18
#define OFF_SKP   24
#define OFF_TKP   (24 + BB*3*KEY)
#define OFF_SKNN  (OFF_TKP + BB*3*KEY)
#define OFF_TKNN  (OFF_SKNN + BB*3*KEY*KC)
#define OFF_LOSS  (OFF_TKNN + BB*3*KEY*KC)

// ---------------- warp mma + cp.async helpers (compute_103-safe) ----------
__device__ __forceinline__ uint32_t smem_u32(const void* p) {
    uint32_t a;
    asm("{ .reg .u64 t; cvta.to.shared.u64 t, %1; cvt.u32.u64 %0, t; }" : "=r"(a) : "l"(p));
    return a;
}
__device__ __forceinline__ void ldsm4(uint32_t* r, uint32_t addr) {
    asm volatile("ldmatrix.sync.aligned.m8n8.x4.shared.b16 {%0,%1,%2,%3}, [%4];"
        : "=r"(r[0]), "=r"(r[1]), "=r"(r[2]), "=r"(r[3]) : "r"(addr));
}
__device__ __forceinline__ void mma16816(float* d, const uint32_t* a, const uint32_t* b) {
    asm volatile(
        "mma.sync.aligned.m16n8k16.row.col.f32.bf16.bf16.f32 "
        "{%0,%1,%2,%3}, {%4,%5,%6,%7}, {%8,%9}, {%0,%1,%2,%3};"
        : "+f"(d[0]), "+f"(d[1]), "+f"(d[2]), "+f"(d[3])
        : "r"(a[0]), "r"(a[1]), "r"(a[2]), "r"(a[3]), "r"(b[0]), "r"(b[1]));
}
__device__ __forceinline__ void cp16(uint32_t saddr, const void* gaddr) {
    asm volatile("cp.async.cg.shared.global [%0], [%1], 16;" :: "r"(saddr), "l"(gaddr));
}
#define CP_COMMIT() asm volatile("cp.async.commit_group;" ::: "memory")
#define CP_WAIT2()  asm volatile("cp.async.wait_group 2;" ::: "memory")

// ================= K0: transpose + 3-way bf16 split prep =================
__global__ __launch_bounds__(256) void k_prep(const float* __restrict__ se,
                                              const float* __restrict__ te) {
    __shared__ float t[32][33];
    int zb = blockIdx.z;
    const float* src = (zb < BB) ? se + (size_t)zb * CC * NN : te + (size_t)(zb - BB) * CC * NN;
    __nv_bfloat16* p1 = (zb < BB) ? g_A1 + (size_t)zb * NN * CC : g_B1 + (size_t)(zb - BB) * NN * CC;
    __nv_bfloat16* p2 = (zb < BB) ? g_A2 + (size_t)zb * NN * CC : g_B2 + (size_t)(zb - BB) * NN * CC;
    __nv_bfloat16* p3 = (zb < BB) ? g_A3 + (size_t)zb * NN * CC : g_B3 + (size_t)(zb - BB) * NN * CC;
    int c0 = blockIdx.x * 32, n0 = blockIdx.y * 32;
    int tx = threadIdx.x & 31, ty = threadIdx.x >> 5;
    #pragma unroll
    for (int i = 0; i < 4; i++)
        t[ty + i * 8][tx] = src[(size_t)(c0 + ty + i * 8) * NN + n0 + tx];
    __syncthreads();
    #pragma unroll
    for (int i = 0; i < 4; i++) {
        int n = n0 + ty + i * 8, c = c0 + tx;
        float v = t[tx][ty + i * 8];
        __nv_bfloat16 h1 = __float2bfloat16(v);
        float r1 = v - __bfloat162float(h1);
        __nv_bfloat16 h2 = __float2bfloat16(r1);
        float r2 = r1 - __bfloat162float(h2);
        __nv_bfloat16 h3 = __float2bfloat16(r2);
        p1[(size_t)n * CC + c] = h1;
        p2[(size_t)n * CC + c] = h2;
        p3[(size_t)n * CC + c] = h3;
    }
}

// ================= K1: column squared norms =================
__global__ void k_norms(const float* __restrict__ se, const float* __restrict__ te) {
    int col = blockIdx.x * blockDim.x + threadIdx.x;
    if (col < BB * NN) {
        int b = col / NN, n = col % NN;
        const float* p = se + (size_t)b * CC * NN + n;
        float s = 0.f;
        for (int c = 0; c < CC; c++) { float v = p[(size_t)c * NN]; s += v * v; }
        g_xx[col] = s;
    } else {
        int c2 = col - BB * NN;
        if (c2 < BB * MM) {
            int b = c2 / MM, m = c2 % MM;
            const float* p = te + (size_t)b * CC * MM + m;
            float s = 0.f;
            for (int c = 0; c < CC; c++) { float v = p[(size_t)c * MM]; s += v * v; }
            g_yy[c2] = s;
        }
    }
}

// ================= K2: bf16x6 HMMA GEMM, 4-stage cp.async, 2 CTA/SM =======
// grid (MM/64, NN/128, BB), block 256 (8 warps: 4 warp_m x 2 warp_n; warp tile 32x32)
#define RS2 24                       // smem row stride in bf16 (48B, ldmatrix conflict-free)
#define TILE_A2 (128 * RS2)          // 3072 elems: A operand tile (128 rows x 16 k)
#define TILE_B2 (64 * RS2)           // 1536 elems
#define STAGE_E (3 * TILE_A2 + 3 * TILE_B2)   // 13824 elems = 27648 B
#define NSTAGE 4
#define NCHUNK (CC / 16)             // 32
__global__ __launch_bounds__(256, 2) void k_gemm() {
    extern __shared__ __align__(16) __nv_bfloat16 sm[];   // 4 stages
    __shared__ float yys[64];

    int tid = threadIdx.x;
    int wid = tid >> 5, lane = tid & 31;
    int warp_m = wid >> 1, warp_n = wid & 1;
    int b = blockIdx.z;
    int m0 = blockIdx.x * 64, n0 = blockIdx.y * 128;

    const __nv_bfloat16* pA[3];
    const __nv_bfloat16* pB[3];
    pA[0] = g_A1 + ((size_t)b * NN + n0) * CC;
    pA[1] = g_A2 + ((size_t)b * NN + n0) * CC;
    pA[2] = g_A3 + ((size_t)b * NN + n0) * CC;
    pB[0] = g_B1 + ((size_t)b * MM + m0) * CC;
    pB[1] = g_B2 + ((size_t)b * MM + m0) * CC;
    pB[2] = g_B3 + ((size_t)b * MM + m0) * CC;

    if (tid < 64) yys[tid] = g_yy[b * MM + m0 + tid];

    float acc[2][4][4];
    #pragma unroll
    for (int mi = 0; mi < 2; mi++)
        #pragma unroll
        for (int ni = 0; ni < 4; ni++)
            #pragma unroll
            for (int q = 0; q < 4; q++) acc[mi][ni][q] = 0.f;

    uint32_t smb = smem_u32(sm);

    // loader mapping: A tile 128 rows x 2 segs (16B); B tile 64 rows x 2 segs
    int arow = tid >> 1, aseg = tid & 1;

    const uint32_t offA[3] = {0, TILE_A2, 2 * TILE_A2};
    const uint32_t offB[3] = {3 * TILE_A2, 3 * TILE_A2 + TILE_B2, 3 * TILE_A2 + 2 * TILE_B2};

    // ldmatrix offsets (bytes within tile)
    uint32_t aoff = (lane & 15) * (RS2 * 2) + (lane >> 4) * 16 + warp_m * 32 * (RS2 * 2);
    // B x4: lanes 0-7: row, col0 | 8-15: row, +16B | 16-23: row+8, col0 | 24-31: row+8, +16B
    uint32_t boff = (lane & 7) * (RS2 * 2) + ((lane >> 3) & 1) * 16
                  + (lane >> 4) * 8 * (RS2 * 2) + warp_n * 32 * (RS2 * 2);

    // ---- prologue: prefetch stages 0..2 ----
    #pragma unroll
    for (int s = 0; s < NSTAGE - 1; s++) {
        uint32_t st = (uint32_t)s * STAGE_E * 2;
        int kn = s * 16;
        #pragma unroll
        for (int t = 0; t < 3; t++) {
            cp16(smb + st + (offA[t] + (uint32_t)(arow * RS2 + aseg * 8)) * 2,
                 pA[t] + (size_t)arow * CC + kn + aseg * 8);
            if (tid < 128)
                cp16(smb + st + (offB[t] + (uint32_t)(arow * RS2 + aseg * 8)) * 2,
                     pB[t] + (size_t)arow * CC + kn + aseg * 8);
        }
        CP_COMMIT();
    }

    for (int kc = 0; kc < NCHUNK; kc++) {
        CP_WAIT2();
        __syncthreads();
        uint32_t stage = (uint32_t)(kc & (NSTAGE - 1)) * STAGE_E * 2;
        // prefetch stage kc+3 (overwrites slot of stage kc-1, done since last sync)
        if (kc + NSTAGE - 1 < NCHUNK) {
            uint32_t nst = (uint32_t)((kc + NSTAGE - 1) & (NSTAGE - 1)) * STAGE_E * 2;
            int kn = (kc + NSTAGE - 1) * 16;
            #pragma unroll
            for (int t = 0; t < 3; t++) {
                cp16(smb + nst + (offA[t] + (uint32_t)(arow * RS2 + aseg * 8)) * 2,
                     pA[t] + (size_t)arow * CC + kn + aseg * 8);
                if (tid < 128)
                    cp16(smb + nst + (offB[t] + (uint32_t)(arow * RS2 + aseg * 8)) * 2,
                         pB[t] + (size_t)arow * CC + kn + aseg * 8);
            }
        }
        CP_COMMIT();   // commit every iteration (possibly empty) to keep group count in step
        // compute current stage (one k16 step)
        uint32_t a1b = smb + stage + offA[0] * 2 + aoff;
        uint32_t a2b = smb + stage + offA[1] * 2 + aoff;
        uint32_t a3b = smb + stage + offA[2] * 2 + aoff;
        uint32_t b1b = smb + stage + offB[0] * 2 + boff;
        uint32_t b2b = smb + stage + offB[1] * 2 + boff;
        uint32_t b3b = smb + stage + offB[2] * 2 + boff;
        uint32_t a1[2][4], a2[2][4], a3[2][4], bf[4][4];  // bf[g] holds ni=2g,2g+1
        #pragma unroll
        for (int mi = 0; mi < 2; mi++) {
            ldsm4(a1[mi], a1b + mi * 16 * (RS2 * 2));
            ldsm4(a2[mi], a2b + mi * 16 * (RS2 * 2));
            ldsm4(a3[mi], a3b + mi * 16 * (RS2 * 2));
        }
        // b1: a1,a2,a3
        #pragma unroll
        for (int g = 0; g < 2; g++)
            ldsm4(bf[g], b1b + g * 16 * (RS2 * 2));
        #pragma unroll
        for (int mi = 0; mi < 2; mi++)
            #pragma unroll
            for (int g = 0; g < 2; g++) {
                mma16816(acc[mi][2 * g + 0], a1[mi], &bf[g][0]);
                mma16816(acc[mi][2 * g + 1], a1[mi], &bf[g][2]);
                mma16816(acc[mi][2 * g + 0], a2[mi], &bf[g][0]);
                mma16816(acc[mi][2 * g + 1], a2[mi], &bf[g][2]);
                mma16816(acc[mi][2 * g + 0], a3[mi], &bf[g][0]);
                mma16816(acc[mi][2 * g + 1], a3[mi], &bf[g][2]);
            }
        // b2: a1,a2
        #pragma unroll
        for (int g = 0; g < 2; g++)
            ldsm4(bf[g], b2b + g * 16 * (RS2 * 2));
        #pragma unroll
        for (int mi = 0; mi < 2; mi++)
            #pragma unroll
            for (int g = 0; g < 2; g++) {
                mma16816(acc[mi][2 * g + 0], a1[mi], &bf[g][0]);
                mma16816(acc[mi][2 * g + 1], a1[mi], &bf[g][2]);
                mma16816(acc[mi][2 * g + 0], a2[mi], &bf[g][0]);
                mma16816(acc[mi][2 * g + 1], a2[mi], &bf[g][2]);
            }
        // b3: a1
        #pragma unroll
        for (int g = 0; g < 2; g++)
            ldsm4(bf[g], b3b + g * 16 * (RS2 * 2));
        #pragma unroll
        for (int mi = 0; mi < 2; mi++)
            #pragma unroll
            for (int g = 0; g < 2; g++) {
                mma16816(acc[mi][2 * g + 0], a1[mi], &bf[g][0]);
                mma16816(acc[mi][2 * g + 1], a1[mi], &bf[g][2]);
            }
        __syncthreads();
    }

    // ---- epilogue: dist = xx - 2*dot + yy ; store e = exp(-dist) ; row partials
    int l4 = lane & 3, l2 = lane >> 2;
    int n_base = n0 + warp_m * 32;
    size_t gb = (size_t)b * NN * MM;
    #pragma unroll
    for (int mi = 0; mi < 2; mi++) {
        #pragma unroll
        for (int half = 0; half < 2; half++) {
            int r = mi * 16 + half * 8 + l2;
            int n = n_base + r;
            float xv = g_xx[b * NN + n];
            float rs = 0.f;
            size_t rowo = gb + (size_t)n * MM + m0 + warp_n * 32;
            #pragma unroll
            for (int ni = 0; ni < 4; ni++) {
                int mc = ni * 8 + l4 * 2;
                float v0 = acc[mi][ni][half * 2 + 0];
                float v1 = acc[mi][ni][half * 2 + 1];
                float d0 = xv - 2.f * v0 + yys[warp_n * 32 + mc];
                float d1 = xv - 2.f * v1 + yys[warp_n * 32 + mc + 1];
                float e0 = expf(-d0), e1 = expf(-d1);
                *(float2*)&g_scores[rowo + mc] = make_float2(e0, e1);
                rs += e0 + e1;
            }
            rs += __shfl_xor_sync(0xffffffffu, rs, 1);
            rs += __shfl_xor_sync(0xffffffffu, rs, 2);
            if (l4 == 0)
                g_rowpart[((size_t)b * NN + n) * 64 + blockIdx.x * 2 + warp_n] = rs;
        }
    }
}

// ================= K3: finalize row inverse sums (warp per row) =========
__global__ __launch_bounds__(256) void k_invsum() {
    int w = (blockIdx.x * 256 + threadIdx.x) >> 5;   // row index
    int lane = threadIdx.x & 31;
    if (w < BB * NN) {
        const float* p = g_rowpart + (size_t)w * 64;
        float s = p[lane] + p[lane + 32];
        #pragma unroll
        for (int sh = 16; sh > 0; sh >>= 1) s += __shfl_xor_sync(0xffffffffu, s, sh);
        if (lane == 0) g_rowinv[w] = 1.f / s;
    }
}

// ================= K4: per-row T/S/refined/rmm pipeline (NT=4) =================
#define NT 4
__global__ __launch_bounds__(256) void k_rowpipe(const float* __restrict__ tgt,
                                                 const int* __restrict__ idx1,
                                                 const int* __restrict__ idx2) {
    int b = blockIdx.y, n0 = blockIdx.x * NT, tid = threadIdx.x;
    __shared__ float4 T4[MM];        // 32KB
    __shared__ float wred[20][8];
    int r[NT][7]; float inv[NT][7];
    #pragma unroll
    for (int nt = 0; nt < NT; nt++) {
        const int* i1 = idx1 + ((size_t)b * NN + n0 + nt) * KK1;
        #pragma unroll
        for (int j = 0; j < 7; j++) {
            r[nt][j] = i1[j + 1];
            inv[nt][j] = g_rowinv[b * NN + r[nt][j]];
        }
    }
    const float* sb = g_scores + (size_t)b * NN * MM;
    for (int m = tid; m < MM; m += 256) {
        float4 t = {0.f, 0.f, 0.f, 0.f};
        #pragma unroll
        for (int j = 0; j < 7; j++) {
            t.x += sb[(size_t)r[0][j] * MM + m] * inv[0][j];
            t.y += sb[(size_t)r[1][j] * MM + m] * inv[1][j];
            t.z += sb[(size_t)r[2][j] * MM + m] * inv[2][j];
            t.w += sb[(size_t)r[3][j] * MM + m] * inv[3][j];
        }
        T4[m] = t;
    }
    __syncthreads();
    const int* ix2 = idx2 + (size_t)b * MM * KK1;
    const float* t0 = tgt + (size_t)b * 3 * MM;
    const float* s0 = sb + (size_t)n0 * MM;
    float sum[NT] = {}, c0[NT] = {}, c1[NT] = {}, c2[NT] = {};
    float mrf[NT] = {1e30f, 1e30f, 1e30f, 1e30f};
    for (int m = tid; m < MM; m += 256) {
        int4 qa = *(const int4*)(ix2 + (size_t)m * KK1);
        int4 qb = *(const int4*)(ix2 + (size_t)m * KK1 + 4);
        float4 S;
        {
            float4 v1 = T4[qa.y], v2 = T4[qa.z], v3 = T4[qa.w];
            float4 v4 = T4[qb.x], v5 = T4[qb.y], v6 = T4[qb.z], v7 = T4[qb.w];
            S.x = v1.x + v2.x + v3.x + v4.x + v5.x + v6.x + v7.x;
            S.y = v1.y + v2.y + v3.y + v4.y + v5.y + v6.y + v7.y;
            S.z = v1.z + v2.z + v3.z + v4.z + v5.z + v6.z + v7.z;
            S.w = v1.w + v2.w + v3.w + v4.w + v5.w + v6.w + v7.w;
        }
        float ty0 = t0[m], ty1 = t0[MM + m], ty2 = t0[2 * MM + m];
        const float* Sp = &S.x;
        #pragma unroll
        for (int nt = 0; nt < NT; nt++) {
            float ein = s0[(size_t)nt * MM + m];
            float d = -logf(ein);                    // recover dist
            float rf = expf(1.0f - Sp[nt] * (1.0f / 7.0f)) * d;
            float e = expf(-rf);
            sum[nt] += e;
            c0[nt] += ty0 * e; c1[nt] += ty1 * e; c2[nt] += ty2 * e;
            mrf[nt] = fminf(mrf[nt], rf);
        }
    }
    int lane = tid & 31, w = tid >> 5;
    #pragma unroll
    for (int nt = 0; nt < NT; nt++) {
        float v0 = sum[nt], v1 = c0[nt], v2 = c1[nt], v3 = c2[nt], v4 = mrf[nt];
        #pragma unroll
        for (int sh = 16; sh > 0; sh >>= 1) {
            v0 += __shfl_xor_sync(0xffffffffu, v0, sh);
            v1 += __shfl_xor_sync(0xffffffffu, v1, sh);
            v2 += __shfl_xor_sync(0xffffffffu, v2, sh);
            v3 += __shfl_xor_sync(0xffffffffu, v3, sh);
            v4 = fminf(v4, __shfl_xor_sync(0xffffffffu, v4, sh));
        }
        if (lane == 0) {
            wred[nt * 5 + 0][w] = v0; wred[nt * 5 + 1][w] = v1;
            wred[nt * 5 + 2][w] = v2; wred[nt * 5 + 3][w] = v3;
            wred[nt * 5 + 4][w] = v4;
        }
    }
    __syncthreads();
    if (tid < NT) {
        int nt = tid;
        float s = 0.f, a0 = 0.f, a1 = 0.f, a2 = 0.f, mn = 1e30f;
        #pragma unroll
        for (int j = 0; j < 8; j++) {
            s  += wred[nt * 5 + 0][j];
            a0 += wred[nt * 5 + 1][j];
            a1 += wred[nt * 5 + 2][j];
            a2 += wred[nt * 5 + 3][j];
            mn = fminf(mn, wred[nt * 5 + 4][j]);
        }
        float is = 1.f / s;
        int n = n0 + nt;
        g_corr[b * 3 * NN + n]          = a0 * is;
        g_corr[b * 3 * NN + NN + n]     = a1 * is;
        g_corr[b * 3 * NN + 2 * NN + n] = a2 * is;
        g_rowmax[b * NN + n] = expf(-mn) * is;
    }
}

// ================= K5: discriminator MLP + max over K =================
__global__ __launch_bounds__(128) void k_disc(const float* __restrict__ src,
                                              const float* __restrict__ src_knn,
                                              const int* __restrict__ src_idx,
                                              const float* __restrict__ W1, const float* __restrict__ b1,
                                              const float* __restrict__ W2, const float* __restrict__ b2,
                                              const float* __restrict__ W3, const float* __restrict__ b3) {
    __shared__ float W2s[H2D * H1D];
    __shared__ float W1s[H1D * 6];
    __shared__ float b1s[H1D];
    __shared__ float W3s[H2D];
    __shared__ float b2s[H2D];
    int tid = threadIdx.x;
    for (int i = tid; i < H2D * H1D; i += 128) W2s[i] = W2[i];
    for (int i = tid; i < H1D * 6; i += 128) W1s[i] = W1[i];
    if (tid < H1D) b1s[tid] = b1[tid];
    if (tid < H2D) { W3s[tid] = W3[tid]; b2s[tid] = b2[tid]; }
    __syncthreads();
    int gp = blockIdx.x * 8 + (tid >> 4);
    int b = gp / NN, n = gp % NN, kk = tid & 15;
    int id = src_idx[((size_t)b * NN + n) * KC + kk];
    const float* cb = g_corr + (size_t)b * 3 * NN;
    const float* sp = src + (size_t)b * 3 * NN;
    const float* skn = src_knn + (((size_t)b * NN + n) * KC + kk) * 3;
    float f[6];
    f[0] = cb[n] - cb[id];
    f[1] = cb[NN + n] - cb[NN + id];
    f[2] = cb[2 * NN + n] - cb[2 * NN + id];
    f[3] = sp[n] - skn[0];
    f[4] = sp[NN + n] - skn[1];
    f[5] = sp[2 * NN + n] - skn[2];
    float h1[H1D];
    #pragma unroll
    for (int d = 0; d < H1D; d++) {
        float a = b1s[d];
        #pragma unroll
        for (int c = 0; c < 6; c++) a += W1s[d * 6 + c] * f[c];
        h1[d] = fmaxf(a, 0.f);
    }
    float s = b3[0];
    for (int e = 0; e < H2D; e++) {
        float a = b2s[e];
        const float4* wr = (const float4*)&W2s[e * H1D];
        #pragma unroll
        for (int d4 = 0; d4 < H1D / 4; d4++) {
            float4 w = wr[d4];
            a += w.x * h1[d4 * 4] + w.y * h1[d4 * 4 + 1] + w.z * h1[d4 * 4 + 2] + w.w * h1[d4 * 4 + 3];
        }
        s += W3s[e] * fmaxf(a, 0.f);
    }
    #pragma unroll
    for (int o = 8; o > 0; o >>= 1) s = fmaxf(s, __shfl_xor_sync(0xffffffffu, s, o));
    if (kk == 0) g_slogit[b * NN + n] = s;
}

// ================= K6: softmax over N -> weight =================
__global__ __launch_bounds__(256) void k_wsoftmax() {
    int b = blockIdx.x, tid = threadIdx.x;
    __shared__ float red[256];
    float mx = -1e30f;
    for (int n = tid; n < NN; n += 256) mx = fmaxf(mx, g_slogit[b * NN + n]);
    red[tid] = mx; __syncthreads();
    for (int s = 128; s > 0; s >>= 1) { if (tid < s) red[tid] = fmaxf(red[tid], red[tid + s]); __syncthreads(); }
    mx = red[0]; __syncthreads();
    float sum = 0.f;
    for (int n = tid; n < NN; n += 256) sum += expf(g_slogit[b * NN + n] - mx);
    red[tid] = sum; __syncthreads();
    for (int s = 128; s > 0; s >>= 1) { if (tid < s) red[tid] += red[tid + s]; __syncthreads(); }
    float inv = 1.f / red[0];
    for (int n = tid; n < NN; n += 256) g_weight[b * NN + n] = expf(g_slogit[b * NN + n] - mx) * inv;
}

// ================= K7: rigid reduction + 3x3 SVD (Kabsch) =================
__device__ double det3d(const double M[3][3]) {
    return M[0][0]*(M[1][1]*M[2][2]-M[1][2]*M[2][1])
         - M[0][1]*(M[1][0]*M[2][2]-M[1][2]*M[2][0])
         + M[0][2]*(M[1][0]*M[2][1]-M[1][1]*M[2][0]);
}
__device__ void jacobi3(double a[3][3], double V[3][3], double w[3]) {
    for (int i = 0; i < 3; i++) for (int j = 0; j < 3; j++) V[i][j] = (i == j) ? 1.0 : 0.0;
    for (int sweep = 0; sweep < 15; sweep++) {
        const int ps[3] = {0, 0, 1}, qs[3] = {1, 2, 2};
        for (int rr = 0; rr < 3; rr++) {
            int p = ps[rr], q = qs[rr];
            double apq = a[p][q];
            if (fabs(apq) < 1e-300) continue;
            double theta = (a[q][q] - a[p][p]) / (2.0 * apq);
            double t = ((theta >= 0.0) ? 1.0 : -1.0) / (fabs(theta) + sqrt(theta * theta + 1.0));
            double c = 1.0 / sqrt(t * t + 1.0);
            double s = t * c;
            for (int k = 0; k < 3; k++) {
                double akp = a[k][p], akq = a[k][q];
                a[k][p] = c * akp - s * akq;
                a[k][q] = s * akp + c * akq;
            }
            for (int k = 0; k < 3; k++) {
                double apk = a[p][k], aqk = a[q][k];
                a[p][k] = c * apk - s * aqk;
                a[q][k] = s * apk + c * aqk;
            }
            for (int k = 0; k < 3; k++) {
                double vkp = V[k][p], vkq = V[k][q];
                V[k][p] = c * vkp - s * vkq;
                V[k][q] = s * vkp + c * vkq;
            }
        }
    }
    for (int i = 0; i < 3; i++) w[i] = a[i][i];
}
__global__ __launch_bounds__(256) void k_rigid(const float* __restrict__ src, float* __restrict__ out) {
    int b = blockIdx.x, tid = threadIdx.x;
    __shared__ float wp[16][8];
    __shared__ double res[16];
    const float* sp = src + (size_t)b * 3 * NN;
    const float* cb = g_corr + (size_t)b * 3 * NN;
    float acc[16] = {};
    for (int n = tid; n < NN; n += 256) {
        float w = g_weight[b * NN + n];
        float s0 = sp[n], s1 = sp[NN + n], s2 = sp[2 * NN + n];
        float c0 = cb[n], c1 = cb[NN + n], c2 = cb[2 * NN + n];
        acc[0] += w;
        acc[1] += w * s0; acc[2] += w * s1; acc[3] += w * s2;
        acc[4] += w * c0; acc[5] += w * c1; acc[6] += w * c2;
        acc[7]  += w * s0 * c0; acc[8]  += w * s0 * c1; acc[9]  += w * s0 * c2;
        acc[10] += w * s1 * c0; acc[11] += w * s1 * c1; acc[12] += w * s1 * c2;
        acc[13] += w * s2 * c0; acc[14] += w * s2 * c1; acc[15] += w * s2 * c2;
    }
    int lane = tid & 31, w8 = tid >> 5;
    #pragma unroll
    for (int q = 0; q < 16; q++) {
        float v = acc[q];
        #pragma unroll
        for (int sh = 16; sh > 0; sh >>= 1) v += __shfl_xor_sync(0xffffffffu, v, sh);
        if (lane == 0) wp[q][w8] = v;
    }
    __syncthreads();
    if (tid < 16) {
        double s = 0.0;
        for (int j = 0; j < 8; j++) s += (double)wp[tid][j];
        res[tid] = s;
    }
    __syncthreads();
    if (tid == 0) {
        double sw = res[0];
        double cs[3], ct[3], H[3][3];
        for (int i = 0; i < 3; i++) { cs[i] = res[1 + i] / sw; ct[i] = res[4 + i] / sw; }
        for (int i = 0; i < 3; i++)
            for (int j = 0; j < 3; j++)
                H[i][j] = res[7 + i * 3 + j] / sw - cs[i] * ct[j];
        double A[3][3];
        for (int i = 0; i < 3; i++)
            for (int j = 0; j < 3; j++) {
                double s = 0;
                for (int k = 0; k < 3; k++) s += H[k][i] * H[k][j];
                A[i][j] = s;
            }
        double V[3][3], wv[3];
        jacobi3(A, V, wv);
        for (int i = 0; i < 2; i++)
            for (int j = i + 1; j < 3; j++)
                if (wv[j] > wv[i]) {
                    double tw = wv[i]; wv[i] = wv[j]; wv[j] = tw;
                    for (int k = 0; k < 3; k++) { double tv = V[k][i]; V[k][i] = V[k][j]; V[k][j] = tv; }
                }
        double sig[3], U[3][3];
        for (int j = 0; j < 3; j++) sig[j] = sqrt(fmax(wv[j], 0.0));
        for (int j = 0; j < 3; j++) {
            double hv[3];
            for (int i = 0; i < 3; i++) {
                double s = 0;
                for (int k = 0; k < 3; k++) s += H[i][k] * V[k][j];
                hv[i] = s;
            }
            if (sig[j] > 1e-12 * fmax(sig[0], 1e-300)) {
                for (int i = 0; i < 3; i++) U[i][j] = hv[i] / sig[j];
            } else {
                U[0][j] = U[1][0] * U[2][1] - U[2][0] * U[1][1];
                U[1][j] = U[2][0] * U[0][1] - U[0][0] * U[2][1];
                U[2][j] = U[0][0] * U[1][1] - U[1][0] * U[0][1];
            }
        }
        double d = det3d(U) * det3d(V);
        double R[3][3];
        for (int i = 0; i < 3; i++)
            for (int k = 0; k < 3; k++)
                R[i][k] = V[i][0] * U[k][0] + V[i][1] * U[k][1] + d * V[i][2] * U[k][2];
        double tvec[3];
        for (int i = 0; i < 3; i++)
            tvec[i] = ct[i] - (R[i][0] * cs[0] + R[i][1] * cs[1] + R[i][2] * cs[2]);
        for (int i = 0; i < 3; i++) {
            for (int j = 0; j < 3; j++) {
                float rv = (float)R[i][j];
                g_R[b * 9 + i * 3 + j] = rv;
                out[OFF_R + b * 9 + i * 3 + j] = rv;
            }
            float tv = (float)tvec[i];
            g_t[b * 3 + i] = tv;
            out[OFF_T + b * 3 + i] = tv;
        }
    }
}

// ================= K8: stable top-k (rank by count), parallel =================
__global__ __launch_bounds__(256) void k_topk() {
    int b = blockIdx.x >> 4;
    int base = (blockIdx.x & 15) * 128;
    int tid = threadIdx.x;
    __shared__ float wsh[NN];
    for (int n = tid; n < NN; n += 256) wsh[n] = g_weight[b * NN + n];
    __syncthreads();
    int n = base + (tid >> 1);
    int half = tid & 1;
    float v = wsh[n];
    int rank = 0;
    int q0 = half * (NN / 2), q1 = q0 + NN / 2;
    for (int q = q0; q < q1; q++) {
        float u = wsh[q];
        rank += (u > v) || (u == v && q < n);
    }
    rank += __shfl_xor_sync(0xffffffffu, rank, 1);
    if (half == 0 && rank < KEY) g_topi[b * KEY + rank] = n;
}

// ================= K9: gather keypoints + knn outputs =================
__global__ __launch_bounds__(256) void k_outputs(const float* __restrict__ src,
                                                 const int* __restrict__ src_idx,
                                                 float* __restrict__ out) {
    int g = blockIdx.x * blockDim.x + threadIdx.x;
    if (g >= BB * KEY * KC) return;
    int kk = g % KC;
    int j = (g / KC) % KEY;
    int b = g / (KC * KEY);
    int tn = g_topi[b * KEY + j];
    const float* sp = src + (size_t)b * 3 * NN;
    const float* cb = g_corr + (size_t)b * 3 * NN;
    int id = src_idx[((size_t)b * NN + tn) * KC + kk];
    const float* R = g_R + b * 9;
    const float* tt = g_t + b * 3;
    float s0 = sp[tn], s1 = sp[NN + tn], s2 = sp[2 * NN + tn];
    float q0 = sp[id], q1 = sp[NN + id], q2 = sp[2 * NN + id];
    float st[3], sq[3];
    #pragma unroll
    for (int c = 0; c < 3; c++) {
        st[c] = R[c * 3] * s0 + R[c * 3 + 1] * s1 + R[c * 3 + 2] * s2 + tt[c];
        sq[c] = R[c * 3] * q0 + R[c * 3 + 1] * q1 + R[c * 3 + 2] * q2 + tt[c];
    }
    float* skk = out + OFF_SKNN;
    float* tkk = out + OFF_TKNN;
    #pragma unroll
    for (int c = 0; c < 3; c++) {
        size_t o = (((size_t)b * 3 + c) * KEY + j) * KC + kk;
        skk[o] = st[c] - sq[c];
        tkk[o] = cb[c * NN + tn] - cb[c * NN + id];
    }
    if (kk == 0) {
        float* skp = out + OFF_SKP;
        float* tkp = out + OFF_TKP;
        #pragma unroll
        for (int c = 0; c < 3; c++) {
            skp[((size_t)b * 3 + c) * KEY + j] = sp[c * NN + tn];
            tkp[((size_t)b * 3 + c) * KEY + j] = cb[c * NN + tn];
        }
    }
}

// ================= K10: loss =================
__global__ __launch_bounds__(256) void k_loss(float* __restrict__ out) {
    __shared__ double red[256];
    int tid = threadIdx.x;
    double s = 0.0;
    for (int p = tid; p < BB * KEY; p += 256) {
        int b = p / KEY;
        int tn = g_topi[p];
        double pm = (double)g_rowmax[b * NN + tn];
        s += -log(pm + 1e-15);
    }
    red[tid] = s; __syncthreads();
    for (int st = 128; st > 0; st >>= 1) { if (tid < st) red[tid] += red[tid + st]; __syncthreads(); }
    if (tid == 0) out[OFF_LOSS] = (float)(red[0] / (double)(BB * KEY));
}

// ================= launch =================
extern "C" void kernel_launch(void* const* d_in, const int* in_sizes, int n_in,
                              void* d_out, int out_size) {
    const float* src      = (const float*)d_in[0];
    const float* tgt      = (const float*)d_in[1];
    const float* se       = (const float*)d_in[2];
    const float* te       = (const float*)d_in[3];
    const float* src_knn  = (const float*)d_in[4];
    const float* W1 = (const float*)d_in[6];
    const float* b1 = (const float*)d_in[7];
    const float* W2 = (const float*)d_in[8];
    const float* b2 = (const float*)d_in[9];
    const float* W3 = (const float*)d_in[10];
    const float* b3 = (const float*)d_in[11];
    const int* src_idx  = (const int*)d_in[12];
    const int* src_idx1 = (const int*)d_in[13];
    const int* idx2     = (const int*)d_in[14];
    float* out = (float*)d_out;

    const int smem_gemm = NSTAGE * STAGE_E * (int)sizeof(__nv_bfloat16);  // 110592 B
    cudaFuncSetAttribute(k_gemm, cudaFuncAttributeMaxDynamicSharedMemorySize, smem_gemm);

    dim3 gp(CC / 32, NN / 32, 2 * BB);
    k_prep<<<gp, 256>>>(se, te);
    k_norms<<<(BB * NN + BB * MM) / 256, 256>>>(se, te);
    dim3 gg(MM / 64, NN / 128, BB);
    k_gemm<<<gg, 256, smem_gemm>>>();
    k_invsum<<<(BB * NN * 32 + 255) / 256, 256>>>();
    dim3 gr(NN / NT, BB);
    k_rowpipe<<<gr, 256>>>(tgt, src_idx1, idx2);
    k_disc<<<BB * NN / 8, 128>>>(src, src_knn, src_idx, W1, b1, W2, b2, W3, b3);
    k_wsoftmax<<<BB, 256>>>();
    k_rigid<<<BB, 256>>>(src, out);
    k_topk<<<BB * 16, 256>>>();
    k_outputs<<<(BB * KEY * KC + 255) / 256, 256>>>(src, src_idx, out);
    k_loss<<<1, 256>>>(out);
}